// round 16
// baseline (speedup 1.0000x reference)
#include <cuda_runtime.h>

// GCMConv on 8x8x16x16 lattice — single fused kernel, T staged in shared memory.
// Block = 32 sites x 128 threads, ONE WAVE: __launch_bounds__(128,4) -> 4 blocks/SM
// -> 592 slots >= 512 blocks.
// Phase 1 (warp=axis a, lane=site): transport T_{a,c} = U_a(x) w_c(x+a) U_a(x)^dag
//   -> smem (computed once per block, shared by all 4 output channels).
// Phase 2 (warp=u, lane=site): M-form contract in FOUR sweeps {0,1,8},{2,3},{4,5},{6,7}
//   (v=8 accumulates straight into acc; M live set = 36 floats -> fits 128 regs).
//   M_v = sum_k c1_{vk} T_k + c2_{vk} T_k^dag (+ c3_v I)
//   w_out[u] = M_8 + sum_c w_c @ M_c + w_c^dag @ M_{4+c}

#define NS 16384

__global__ __launch_bounds__(128, 4) void gcm_kernel(const float* __restrict__ x,
                                                     const float* __restrict__ weight,
                                                     float* __restrict__ out) {
    __shared__ float2 Ts[16 * 9 * 32];   // [(k*9+m)*32 + lane] transported matrices
    __shared__ float2 Wcs[4 * 9 * 32];   // [(c*9+m)*32 + lane] own-site fields
    __shared__ float  wt[4 * 297];       // [u*297 + w*9 + v] transposed weights

    const int tid = threadIdx.x;
    const int lane = tid & 31;           // site within block
    const int wrp = tid >> 5;            // a (phase 1) / u (phase 2)
    const int siteBase = blockIdx.x * 32;
    const int site = siteBase + lane;

    // ---- stage weights (transposed per u) ----
    for (int s = tid; s < 4 * 297; s += 128) {
        int u = s / 297, rem = s % 297;
        int v = rem / 33, w = rem % 33;
        wt[u * 297 + w * 9 + v] = weight[u * 297 + rem];
    }

    // ---- coalesced U-copy: channels 0..3 (first 72 floats of each site) ----
    {
        const float4* x4 = reinterpret_cast<const float4*>(x);
        float4* o4 = reinterpret_cast<float4*>(out);
        for (int f = tid; f < 32 * 18; f += 128) {
            int s = f / 18, c4 = f % 18;
            o4[(siteBase + s) * 36 + c4] = x4[(siteBase + s) * 36 + c4];
        }
    }

    // ================= Phase 1: transport (warp = axis a) =================
    {
        const int a = wrp;
        // periodic +1 neighbor; dims (8,8,16,16), strides (2048,256,16,1)
        int d3 = site & 15, d2 = (site >> 4) & 15, d1 = (site >> 8) & 7, d0 = (site >> 11) & 7;
        int nbr;
        if (a == 0)      nbr = site + ((((d0 + 1) & 7) - d0) << 11);
        else if (a == 1) nbr = site + ((((d1 + 1) & 7) - d1) << 8);
        else if (a == 2) nbr = site + ((((d2 + 1) & 15) - d2) << 4);
        else             nbr = site + (((d3 + 1) & 15) - d3);

        float Ur[3][3], Ui[3][3];
        {
            const float2* up = (const float2*)(x + site * 144 + a * 18);
#pragma unroll
            for (int m = 0; m < 9; m++) {
                float2 t = up[m];
                Ur[m / 3][m % 3] = t.x;
                Ui[m / 3][m % 3] = t.y;
            }
        }

#pragma unroll
        for (int c = 0; c < 4; c++) {
            float Wr[3][3], Wi[3][3];
            const float2* wp = (const float2*)(x + nbr * 144 + (4 + c) * 18);
#pragma unroll
            for (int m = 0; m < 9; m++) {
                float2 t = wp[m];
                Wr[m / 3][m % 3] = t.x;
                Wi[m / 3][m % 3] = t.y;
            }
            // t1 = U @ W
            float t1r[3][3], t1i[3][3];
#pragma unroll
            for (int i = 0; i < 3; i++)
#pragma unroll
                for (int kk = 0; kk < 3; kk++) {
                    float cr = 0.f, ci = 0.f;
#pragma unroll
                    for (int j = 0; j < 3; j++) {
                        cr += Ur[i][j] * Wr[j][kk] - Ui[i][j] * Wi[j][kk];
                        ci += Ur[i][j] * Wi[j][kk] + Ui[i][j] * Wr[j][kk];
                    }
                    t1r[i][kk] = cr;
                    t1i[i][kk] = ci;
                }
            // T = t1 @ U^dag -> smem
            int r = a * 4 + c;
#pragma unroll
            for (int i = 0; i < 3; i++)
#pragma unroll
                for (int kk = 0; kk < 3; kk++) {
                    float cr = 0.f, ci = 0.f;
#pragma unroll
                    for (int j = 0; j < 3; j++) {
                        float br = Ur[kk][j], bi = -Ui[kk][j];
                        cr += t1r[i][j] * br - t1i[i][j] * bi;
                        ci += t1r[i][j] * bi + t1i[i][j] * br;
                    }
                    Ts[(r * 9 + i * 3 + kk) * 32 + lane] = make_float2(cr, ci);
                }
        }

        // own-site field copy: channel c = a
        {
            const float2* wp = (const float2*)(x + site * 144 + (4 + a) * 18);
#pragma unroll
            for (int m = 0; m < 9; m++)
                Wcs[(a * 9 + m) * 32 + lane] = wp[m];
        }
    }
    __syncthreads();

    // ================= Phase 2: contract (warp = u) =================
    const int u = wrp;
    const float* wtu = wt + u * 297;

    float accr[3][3], acci[3][3];
#pragma unroll
    for (int i = 0; i < 3; i++)
#pragma unroll
        for (int j = 0; j < 3; j++) { accr[i][j] = 0.f; acci[i][j] = 0.f; }

    // Four sweeps: sweep 0 handles v-pair {0,1} plus v=8 (into acc directly);
    // sweeps 1..3 handle v-pairs {2,3},{4,5},{6,7}.
#pragma unroll
    for (int sw = 0; sw < 4; sw++) {
        const int v0 = 2 * sw;
        float Mr[2][9], Mi[2][9];
#pragma unroll
        for (int t = 0; t < 2; t++)
#pragma unroll
            for (int m = 0; m < 9; m++) { Mr[t][m] = 0.f; Mi[t][m] = 0.f; }

#pragma unroll 2
        for (int k = 0; k < 16; k++) {
            float2 T[9];
#pragma unroll
            for (int m = 0; m < 9; m++)
                T[m] = Ts[(k * 9 + m) * 32 + lane];

#pragma unroll
            for (int t = 0; t < 2; t++) {
                const int v = v0 + t;
                float c1 = wtu[k * 9 + v];
                float c2 = wtu[(16 + k) * 9 + v];
#pragma unroll
                for (int i = 0; i < 3; i++)
#pragma unroll
                    for (int j = 0; j < 3; j++) {
                        Mr[t][i * 3 + j] += c1 * T[i * 3 + j].x + c2 * T[j * 3 + i].x;
                        Mi[t][i * 3 + j] += c1 * T[i * 3 + j].y - c2 * T[j * 3 + i].y;
                    }
            }
            if (sw == 0) {
                // v = 8 accumulates straight into acc
                float c1 = wtu[k * 9 + 8];
                float c2 = wtu[(16 + k) * 9 + 8];
#pragma unroll
                for (int i = 0; i < 3; i++)
#pragma unroll
                    for (int j = 0; j < 3; j++) {
                        accr[i][j] += c1 * T[i * 3 + j].x + c2 * T[j * 3 + i].x;
                        acci[i][j] += c1 * T[i * 3 + j].y - c2 * T[j * 3 + i].y;
                    }
            }
        }
        if (sw == 0) {
            float c3 = wtu[288 + 8];
            accr[0][0] += c3; accr[1][1] += c3; accr[2][2] += c3;
        }

        // epilogue: N = M + c3 I ; acc += A_v @ N for the two v of this sweep
#pragma unroll
        for (int t = 0; t < 2; t++) {
            const int v = v0 + t;
            float c3 = wtu[288 + v];
            float nr[3][3], ni[3][3];
#pragma unroll
            for (int i = 0; i < 3; i++)
#pragma unroll
                for (int j = 0; j < 3; j++) {
                    nr[i][j] = Mr[t][i * 3 + j] + ((i == j) ? c3 : 0.f);
                    ni[i][j] = Mi[t][i * 3 + j];
                }

            const int c = (v < 4) ? v : (v - 4);
            float wr[3][3], wi[3][3];
#pragma unroll
            for (int m = 0; m < 9; m++) {
                float2 t2 = Wcs[(c * 9 + m) * 32 + lane];
                wr[m / 3][m % 3] = t2.x;
                wi[m / 3][m % 3] = t2.y;
            }
            if (v < 4) {
                // acc += w_c @ N
#pragma unroll
                for (int i = 0; i < 3; i++)
#pragma unroll
                    for (int kk = 0; kk < 3; kk++) {
                        float cr = accr[i][kk], ci = acci[i][kk];
#pragma unroll
                        for (int j = 0; j < 3; j++) {
                            cr += wr[i][j] * nr[j][kk] - wi[i][j] * ni[j][kk];
                            ci += wr[i][j] * ni[j][kk] + wi[i][j] * nr[j][kk];
                        }
                        accr[i][kk] = cr; acci[i][kk] = ci;
                    }
            } else {
                // acc += w_c^dag @ N : conj(w[j][i]) * N[j][kk]
#pragma unroll
                for (int i = 0; i < 3; i++)
#pragma unroll
                    for (int kk = 0; kk < 3; kk++) {
                        float cr = accr[i][kk], ci = acci[i][kk];
#pragma unroll
                        for (int j = 0; j < 3; j++) {
                            cr += wr[j][i] * nr[j][kk] + wi[j][i] * ni[j][kk];
                            ci += wr[j][i] * ni[j][kk] - wi[j][i] * nr[j][kk];
                        }
                        accr[i][kk] = cr; acci[i][kk] = ci;
                    }
            }
        }
    }

    float2* dst = (float2*)(out + site * 144 + (4 + u) * 18);
#pragma unroll
    for (int i = 0; i < 3; i++)
#pragma unroll
        for (int j = 0; j < 3; j++)
            dst[i * 3 + j] = make_float2(accr[i][j], acci[i][j]);
}

extern "C" void kernel_launch(void* const* d_in, const int* in_sizes, int n_in,
                              void* d_out, int out_size) {
    const float* x = (const float*)d_in[0];
    const float* weight = (const float*)d_in[1];
    float* out = (float*)d_out;

    gcm_kernel<<<NS / 32, 128>>>(x, weight, out);
}

// round 17
// speedup vs baseline: 1.3309x; 1.3309x over previous
#include <cuda_runtime.h>

// GCMConv on 8x8x16x16 lattice — single fused kernel, T staged in shared memory
// in a symmetric/antisymmetric basis that HALVES the contract FLOPs.
// Block = 32 sites x 128 threads, __launch_bounds__(128,3) (R15-proven).
//
// Phase 1 (warp=axis a, lane=site): T_{a,c} = U_a(x) w_c(x+a) U_a(x)^dag, stored as
//   S[ij] = T[ij]+T[ji] (m=0..2 diag doubled, m=3..5 upper), D[ij] = T[ij]-T[ji] (q=0..2).
// Phase 2 (warp=u, lane=site), weights pre-folded cp=(c1+c2)/2, cm=(c1-c2)/2:
//   re: MS_r += cp*S_r, MD_r += cm*D_r ; im: MS_i += cm*S_i, MD_i += cp*D_i
//   (18 FFMA per (v,k) instead of 36). Reconstruct M[ij] = MS +/- MD at epilogue.
//   w_out[u] = M_8 + sum_c w_c @ M_c + w_c^dag @ M_{4+c}  (+ c3_v I terms)

#define NS 16384

__global__ __launch_bounds__(128, 3) void gcm_kernel(const float* __restrict__ x,
                                                     const float* __restrict__ weight,
                                                     float* __restrict__ out) {
    __shared__ float2 Ts[16 * 9 * 32];   // [(k*9+m)*32+lane]: m<6 -> (Sr,Si), m>=6 -> (Dr,Di)
    __shared__ float2 Wcs[4 * 9 * 32];   // [(c*9+m)*32+lane] own-site fields
    __shared__ float  wt[4 * 297];       // [u*297 + k*9 + v]=cp, [(16+k)*9+v]=cm, [288+v]=c3

    const int tid = threadIdx.x;
    const int lane = tid & 31;           // site within block
    const int wrp = tid >> 5;            // a (phase 1) / u (phase 2)
    const int siteBase = blockIdx.x * 32;
    const int site = siteBase + lane;

    // ---- stage folded weights: cp/cm pairs + c3 ----
    for (int s = tid; s < 576; s += 128) {          // (u, v, k) triples
        int u = s / 144, rem = s % 144;
        int v = rem / 16, k = rem % 16;
        float c1 = weight[u * 297 + v * 33 + k];
        float c2 = weight[u * 297 + v * 33 + 16 + k];
        wt[u * 297 + k * 9 + v] = 0.5f * (c1 + c2);
        wt[u * 297 + (16 + k) * 9 + v] = 0.5f * (c1 - c2);
    }
    if (tid < 36) {
        int u = tid / 9, v = tid % 9;
        wt[u * 297 + 288 + v] = weight[u * 297 + v * 33 + 32];
    }

    // ---- coalesced U-copy: channels 0..3 (first 72 floats of each site) ----
    {
        const float4* x4 = reinterpret_cast<const float4*>(x);
        float4* o4 = reinterpret_cast<float4*>(out);
        for (int f = tid; f < 32 * 18; f += 128) {
            int s = f / 18, c4 = f % 18;
            o4[(siteBase + s) * 36 + c4] = x4[(siteBase + s) * 36 + c4];
        }
    }

    // ================= Phase 1: transport (warp = axis a) =================
    {
        const int a = wrp;
        // periodic +1 neighbor; dims (8,8,16,16), strides (2048,256,16,1)
        int d3 = site & 15, d2 = (site >> 4) & 15, d1 = (site >> 8) & 7, d0 = (site >> 11) & 7;
        int nbr;
        if (a == 0)      nbr = site + ((((d0 + 1) & 7) - d0) << 11);
        else if (a == 1) nbr = site + ((((d1 + 1) & 7) - d1) << 8);
        else if (a == 2) nbr = site + ((((d2 + 1) & 15) - d2) << 4);
        else             nbr = site + (((d3 + 1) & 15) - d3);

        float Ur[3][3], Ui[3][3];
        {
            const float2* up = (const float2*)(x + site * 144 + a * 18);
#pragma unroll
            for (int m = 0; m < 9; m++) {
                float2 t = up[m];
                Ur[m / 3][m % 3] = t.x;
                Ui[m / 3][m % 3] = t.y;
            }
        }

#pragma unroll
        for (int c = 0; c < 4; c++) {
            float Wr[3][3], Wi[3][3];
            const float2* wp = (const float2*)(x + nbr * 144 + (4 + c) * 18);
#pragma unroll
            for (int m = 0; m < 9; m++) {
                float2 t = wp[m];
                Wr[m / 3][m % 3] = t.x;
                Wi[m / 3][m % 3] = t.y;
            }
            // t1 = U @ W
            float t1r[3][3], t1i[3][3];
#pragma unroll
            for (int i = 0; i < 3; i++)
#pragma unroll
                for (int kk = 0; kk < 3; kk++) {
                    float cr = 0.f, ci = 0.f;
#pragma unroll
                    for (int j = 0; j < 3; j++) {
                        cr += Ur[i][j] * Wr[j][kk] - Ui[i][j] * Wi[j][kk];
                        ci += Ur[i][j] * Wi[j][kk] + Ui[i][j] * Wr[j][kk];
                    }
                    t1r[i][kk] = cr;
                    t1i[i][kk] = ci;
                }
            // T = t1 @ U^dag, then store S/D basis
            float Tr[3][3], Ti[3][3];
#pragma unroll
            for (int i = 0; i < 3; i++)
#pragma unroll
                for (int kk = 0; kk < 3; kk++) {
                    float cr = 0.f, ci = 0.f;
#pragma unroll
                    for (int j = 0; j < 3; j++) {
                        float br = Ur[kk][j], bi = -Ui[kk][j];
                        cr += t1r[i][j] * br - t1i[i][j] * bi;
                        ci += t1r[i][j] * bi + t1i[i][j] * br;
                    }
                    Tr[i][kk] = cr;
                    Ti[i][kk] = ci;
                }
            int r = a * 4 + c;
            // m = 0..2: diag doubled
            Ts[(r * 9 + 0) * 32 + lane] = make_float2(2.f * Tr[0][0], 2.f * Ti[0][0]);
            Ts[(r * 9 + 1) * 32 + lane] = make_float2(2.f * Tr[1][1], 2.f * Ti[1][1]);
            Ts[(r * 9 + 2) * 32 + lane] = make_float2(2.f * Tr[2][2], 2.f * Ti[2][2]);
            // m = 3..5: S upper (01, 02, 12)
            Ts[(r * 9 + 3) * 32 + lane] = make_float2(Tr[0][1] + Tr[1][0], Ti[0][1] + Ti[1][0]);
            Ts[(r * 9 + 4) * 32 + lane] = make_float2(Tr[0][2] + Tr[2][0], Ti[0][2] + Ti[2][0]);
            Ts[(r * 9 + 5) * 32 + lane] = make_float2(Tr[1][2] + Tr[2][1], Ti[1][2] + Ti[2][1]);
            // m = 6..8: D upper (01, 02, 12)
            Ts[(r * 9 + 6) * 32 + lane] = make_float2(Tr[0][1] - Tr[1][0], Ti[0][1] - Ti[1][0]);
            Ts[(r * 9 + 7) * 32 + lane] = make_float2(Tr[0][2] - Tr[2][0], Ti[0][2] - Ti[2][0]);
            Ts[(r * 9 + 8) * 32 + lane] = make_float2(Tr[1][2] - Tr[2][1], Ti[1][2] - Ti[2][1]);
        }

        // own-site field copy: channel c = a
        {
            const float2* wp = (const float2*)(x + site * 144 + (4 + a) * 18);
#pragma unroll
            for (int m = 0; m < 9; m++)
                Wcs[(a * 9 + m) * 32 + lane] = wp[m];
        }
    }
    __syncthreads();

    // ================= Phase 2: contract (warp = u) =================
    const int u = wrp;
    const float* wtu = wt + u * 297;

    float accr[3][3], acci[3][3];
#pragma unroll
    for (int i = 0; i < 3; i++)
#pragma unroll
        for (int j = 0; j < 3; j++) { accr[i][j] = 0.f; acci[i][j] = 0.f; }

    // 3 passes over v-groups {0,1,2}, {3,4,5}, {6,7,8}
#pragma unroll
    for (int vb = 0; vb < 9; vb += 3) {
        // per-v accumulators in S/D basis: MSr[6], MSi[6], MDr[3], MDi[3]
        float MSr[3][6], MSi[3][6], MDr[3][3], MDi[3][3];
#pragma unroll
        for (int t = 0; t < 3; t++) {
#pragma unroll
            for (int m = 0; m < 6; m++) { MSr[t][m] = 0.f; MSi[t][m] = 0.f; }
#pragma unroll
            for (int q = 0; q < 3; q++) { MDr[t][q] = 0.f; MDi[t][q] = 0.f; }
        }

#pragma unroll 2
        for (int k = 0; k < 16; k++) {
            float2 T[9];
#pragma unroll
            for (int m = 0; m < 9; m++)
                T[m] = Ts[(k * 9 + m) * 32 + lane];

#pragma unroll
            for (int t = 0; t < 3; t++) {
                const int v = vb + t;
                float cp = wtu[k * 9 + v];
                float cm = wtu[(16 + k) * 9 + v];
#pragma unroll
                for (int m = 0; m < 6; m++) {
                    MSr[t][m] += cp * T[m].x;
                    MSi[t][m] += cm * T[m].y;
                }
#pragma unroll
                for (int q = 0; q < 3; q++) {
                    MDr[t][q] += cm * T[6 + q].x;
                    MDi[t][q] += cp * T[6 + q].y;
                }
            }
        }

        // epilogue: reconstruct N = M + c3 I ; acc += A_v @ N
#pragma unroll
        for (int t = 0; t < 3; t++) {
            const int v = vb + t;
            float c3 = wtu[288 + v];
            float nr[3][3], ni[3][3];
            nr[0][0] = MSr[t][0] + c3; ni[0][0] = MSi[t][0];
            nr[1][1] = MSr[t][1] + c3; ni[1][1] = MSi[t][1];
            nr[2][2] = MSr[t][2] + c3; ni[2][2] = MSi[t][2];
            nr[0][1] = MSr[t][3] + MDr[t][0]; nr[1][0] = MSr[t][3] - MDr[t][0];
            ni[0][1] = MSi[t][3] + MDi[t][0]; ni[1][0] = MSi[t][3] - MDi[t][0];
            nr[0][2] = MSr[t][4] + MDr[t][1]; nr[2][0] = MSr[t][4] - MDr[t][1];
            ni[0][2] = MSi[t][4] + MDi[t][1]; ni[2][0] = MSi[t][4] - MDi[t][1];
            nr[1][2] = MSr[t][5] + MDr[t][2]; nr[2][1] = MSr[t][5] - MDr[t][2];
            ni[1][2] = MSi[t][5] + MDi[t][2]; ni[2][1] = MSi[t][5] - MDi[t][2];

            if (v == 8) {
#pragma unroll
                for (int i = 0; i < 3; i++)
#pragma unroll
                    for (int j = 0; j < 3; j++) { accr[i][j] += nr[i][j]; acci[i][j] += ni[i][j]; }
            } else {
                const int c = (v < 4) ? v : (v - 4);
                float wr[3][3], wi[3][3];
#pragma unroll
                for (int m = 0; m < 9; m++) {
                    float2 t2 = Wcs[(c * 9 + m) * 32 + lane];
                    wr[m / 3][m % 3] = t2.x;
                    wi[m / 3][m % 3] = t2.y;
                }
                if (v < 4) {
                    // acc += w_c @ N
#pragma unroll
                    for (int i = 0; i < 3; i++)
#pragma unroll
                        for (int kk = 0; kk < 3; kk++) {
                            float cr = accr[i][kk], ci = acci[i][kk];
#pragma unroll
                            for (int j = 0; j < 3; j++) {
                                cr += wr[i][j] * nr[j][kk] - wi[i][j] * ni[j][kk];
                                ci += wr[i][j] * ni[j][kk] + wi[i][j] * nr[j][kk];
                            }
                            accr[i][kk] = cr; acci[i][kk] = ci;
                        }
                } else {
                    // acc += w_c^dag @ N : conj(w[j][i]) * N[j][kk]
#pragma unroll
                    for (int i = 0; i < 3; i++)
#pragma unroll
                        for (int kk = 0; kk < 3; kk++) {
                            float cr = accr[i][kk], ci = acci[i][kk];
#pragma unroll
                            for (int j = 0; j < 3; j++) {
                                cr += wr[j][i] * nr[j][kk] + wi[j][i] * ni[j][kk];
                                ci += wr[j][i] * ni[j][kk] - wi[j][i] * nr[j][kk];
                            }
                            accr[i][kk] = cr; acci[i][kk] = ci;
                        }
                }
            }
        }
    }

    float2* dst = (float2*)(out + site * 144 + (4 + u) * 18);
#pragma unroll
    for (int i = 0; i < 3; i++)
#pragma unroll
        for (int j = 0; j < 3; j++)
            dst[i * 3 + j] = make_float2(accr[i][j], acci[i][j]);
}

extern "C" void kernel_launch(void* const* d_in, const int* in_sizes, int n_in,
                              void* d_out, int out_size) {
    const float* x = (const float*)d_in[0];
    const float* weight = (const float*)d_in[1];
    float* out = (float*)d_out;

    gcm_kernel<<<NS / 32, 128>>>(x, weight, out);
}